// round 1
// baseline (speedup 1.0000x reference)
#include <cuda_runtime.h>
#include <math.h>

// Problem constants (fixed by the dataset).
#define MTOK 16384        // B*N tokens
#define DDIM 1024         // hidden dim
#define NEXP 8            // experts
#define FDIM 512          // expert dim
#define KEF  4096         // NEXP*FDIM

// Scratch: router weights + scaled/activated hidden state G[t, e*F+f].
__device__ float g_router[MTOK * NEXP];
__device__ float g_hidden[(size_t)MTOK * KEF];   // 256 MB

// ---------------------------------------------------------------------------
// Router: per-token logits over 8 experts + softmax.
// One block per token, 8 warps = 8 experts.
// ---------------------------------------------------------------------------
__global__ void __launch_bounds__(256) router_kernel(
    const float* __restrict__ x,    // [MTOK, DDIM]
    const float* __restrict__ Wr,   // [DDIM, NEXP]
    const float* __restrict__ br)   // [NEXP]
{
    const int t = blockIdx.x;
    __shared__ float xs[DDIM];
    __shared__ float logits[NEXP];

    const float* xrow = x + (size_t)t * DDIM;
    for (int i = threadIdx.x; i < DDIM; i += blockDim.x) xs[i] = xrow[i];
    __syncthreads();

    const int warp = threadIdx.x >> 5;   // expert id
    const int lane = threadIdx.x & 31;
    float acc = 0.0f;
    for (int k = lane; k < DDIM; k += 32)
        acc = fmaf(xs[k], Wr[k * NEXP + warp], acc);
    #pragma unroll
    for (int o = 16; o > 0; o >>= 1)
        acc += __shfl_xor_sync(0xffffffffu, acc, o);
    if (lane == 0) logits[warp] = acc + br[warp];
    __syncthreads();

    if (threadIdx.x == 0) {
        float mx = logits[0];
        #pragma unroll
        for (int e = 1; e < NEXP; e++) mx = fmaxf(mx, logits[e]);
        float ex[NEXP]; float s = 0.0f;
        #pragma unroll
        for (int e = 0; e < NEXP; e++) { ex[e] = expf(logits[e] - mx); s += ex[e]; }
        float inv = 1.0f / s;
        #pragma unroll
        for (int e = 0; e < NEXP; e++) g_router[t * NEXP + e] = ex[e] * inv;
    }
}

// ---------------------------------------------------------------------------
// FC1 grouped GEMM: G[m, e*F+n] = w[m,e] * gelu(x[m,:]@W1[e,:,n] + b1[e,n])
// 128x128 tile, BK=8, 256 threads, 8x8 per-thread register tile.
// grid = (F/128, M/128, E). All dims divide evenly -> no bounds checks.
// ---------------------------------------------------------------------------
__global__ void __launch_bounds__(256) moe_fc1_kernel(
    const float* __restrict__ x,    // [MTOK, DDIM]
    const float* __restrict__ W1,   // [NEXP, DDIM, FDIM]
    const float* __restrict__ b1)   // [NEXP, FDIM]
{
    const int e   = blockIdx.z;
    const int bn0 = blockIdx.x * 128;
    const int bm0 = blockIdx.y * 128;

    const float* A = x;                                  // lda = DDIM
    const float* B = W1 + (size_t)e * DDIM * FDIM;       // [DDIM, FDIM], ldb = FDIM

    __shared__ float As[8][128];   // A tile, transposed [k][m]
    __shared__ float Bs[8][128];   // B tile [k][n]

    float acc[8][8] = {};

    const int tid  = threadIdx.x;
    const int trow = (tid >> 4) << 3;      // 0..120
    const int tcol = (tid & 15) << 3;      // 0..120
    const int aRow = tid >> 1;             // 0..127
    const int aCol = (tid & 1) << 2;       // 0 or 4
    const int bRow = tid >> 5;             // 0..7
    const int bCol = (tid & 31) << 2;      // 0..124

    for (int k0 = 0; k0 < DDIM; k0 += 8) {
        float4 av = *(const float4*)(A + (size_t)(bm0 + aRow) * DDIM + k0 + aCol);
        As[aCol + 0][aRow] = av.x;
        As[aCol + 1][aRow] = av.y;
        As[aCol + 2][aRow] = av.z;
        As[aCol + 3][aRow] = av.w;
        *(float4*)(&Bs[bRow][bCol]) =
            *(const float4*)(B + (size_t)(k0 + bRow) * FDIM + bn0 + bCol);
        __syncthreads();

        #pragma unroll
        for (int k = 0; k < 8; k++) {
            float4 a0 = *(const float4*)(&As[k][trow]);
            float4 a1 = *(const float4*)(&As[k][trow + 4]);
            float4 b0 = *(const float4*)(&Bs[k][tcol]);
            float4 b1v = *(const float4*)(&Bs[k][tcol + 4]);
            float a[8] = {a0.x, a0.y, a0.z, a0.w, a1.x, a1.y, a1.z, a1.w};
            float b[8] = {b0.x, b0.y, b0.z, b0.w, b1v.x, b1v.y, b1v.z, b1v.w};
            #pragma unroll
            for (int i = 0; i < 8; i++)
                #pragma unroll
                for (int j = 0; j < 8; j++)
                    acc[i][j] = fmaf(a[i], b[j], acc[i][j]);
        }
        __syncthreads();
    }

    // Epilogue: +bias, exact gelu, scale by router weight, write to scratch.
    #pragma unroll
    for (int i = 0; i < 8; i++) {
        const int m = bm0 + trow + i;
        const float w = g_router[m * NEXP + e];
        #pragma unroll
        for (int j = 0; j < 8; j++) {
            const int n = bn0 + tcol + j;
            float v = acc[i][j] + b1[e * FDIM + n];
            v = 0.5f * v * (1.0f + erff(v * 0.70710678118654752f));  // exact gelu
            g_hidden[(size_t)m * KEF + e * FDIM + n] = v * w;
        }
    }
}

// ---------------------------------------------------------------------------
// FC2 GEMM: out[m,n] = G[m,:] @ W2flat[:,n] + sum_e w[m,e]*b2[e,n]
// W2 [E,F,D] is contiguous == W2flat [E*F, D]. Same tiling, K = 4096.
// grid = (D/128, M/128).
// ---------------------------------------------------------------------------
__global__ void __launch_bounds__(256) moe_fc2_kernel(
    const float* __restrict__ W2,   // [KEF, DDIM] (flat view of [E,F,D])
    const float* __restrict__ b2,   // [NEXP, DDIM]
    float* __restrict__ out)        // [MTOK, DDIM]
{
    const int bn0 = blockIdx.x * 128;
    const int bm0 = blockIdx.y * 128;

    const float* A = g_hidden;      // lda = KEF
    const float* B = W2;            // ldb = DDIM

    __shared__ float As[8][128];
    __shared__ float Bs[8][128];
    __shared__ float b2s[NEXP][128];   // bias tile for this n-range

    float acc[8][8] = {};

    const int tid  = threadIdx.x;
    const int trow = (tid >> 4) << 3;
    const int tcol = (tid & 15) << 3;
    const int aRow = tid >> 1;
    const int aCol = (tid & 1) << 2;
    const int bRow = tid >> 5;
    const int bCol = (tid & 31) << 2;

    // Load bias tile once: 8 experts x 128 cols = 256 float4s = 1 per thread.
    {
        const int be = tid >> 5;           // 0..7
        const int bc = (tid & 31) << 2;    // 0..124
        *(float4*)(&b2s[be][bc]) = *(const float4*)(b2 + (size_t)be * DDIM + bn0 + bc);
    }

    for (int k0 = 0; k0 < KEF; k0 += 8) {
        float4 av = *(const float4*)(A + (size_t)(bm0 + aRow) * KEF + k0 + aCol);
        As[aCol + 0][aRow] = av.x;
        As[aCol + 1][aRow] = av.y;
        As[aCol + 2][aRow] = av.z;
        As[aCol + 3][aRow] = av.w;
        *(float4*)(&Bs[bRow][bCol]) =
            *(const float4*)(B + (size_t)(k0 + bRow) * DDIM + bn0 + bCol);
        __syncthreads();

        #pragma unroll
        for (int k = 0; k < 8; k++) {
            float4 a0 = *(const float4*)(&As[k][trow]);
            float4 a1 = *(const float4*)(&As[k][trow + 4]);
            float4 b0 = *(const float4*)(&Bs[k][tcol]);
            float4 b1v = *(const float4*)(&Bs[k][tcol + 4]);
            float a[8] = {a0.x, a0.y, a0.z, a0.w, a1.x, a1.y, a1.z, a1.w};
            float b[8] = {b0.x, b0.y, b0.z, b0.w, b1v.x, b1v.y, b1v.z, b1v.w};
            #pragma unroll
            for (int i = 0; i < 8; i++)
                #pragma unroll
                for (int j = 0; j < 8; j++)
                    acc[i][j] = fmaf(a[i], b[j], acc[i][j]);
        }
        __syncthreads();
    }

    // Epilogue: add softmax-weighted bias combine, write output.
    #pragma unroll
    for (int i = 0; i < 8; i++) {
        const int m = bm0 + trow + i;
        float wr[NEXP];
        #pragma unroll
        for (int ee = 0; ee < NEXP; ee++) wr[ee] = g_router[m * NEXP + ee];
        #pragma unroll
        for (int j = 0; j < 8; j++) {
            const int n = bn0 + tcol + j;
            float bias = 0.0f;
            #pragma unroll
            for (int ee = 0; ee < NEXP; ee++)
                bias = fmaf(wr[ee], b2s[ee][tcol + j], bias);
            out[(size_t)m * DDIM + n] = acc[i][j] + bias;
        }
    }
}

// ---------------------------------------------------------------------------
extern "C" void kernel_launch(void* const* d_in, const int* in_sizes, int n_in,
                              void* d_out, int out_size)
{
    const float* x  = (const float*)d_in[0];
    const float* W1 = (const float*)d_in[1];
    const float* b1 = (const float*)d_in[2];
    const float* W2 = (const float*)d_in[3];
    const float* b2 = (const float*)d_in[4];
    const float* Wr = (const float*)d_in[5];
    const float* br = (const float*)d_in[6];
    float* out = (float*)d_out;

    router_kernel<<<MTOK, 256>>>(x, Wr, br);

    dim3 g1(FDIM / 128, MTOK / 128, NEXP);   // (4, 128, 8)
    moe_fc1_kernel<<<g1, 256>>>(x, W1, b1);

    dim3 g2(DDIM / 128, MTOK / 128);          // (8, 128)
    moe_fc2_kernel<<<g2, 256>>>(W2, b2, out);
}

// round 3
// speedup vs baseline: 3.2145x; 3.2145x over previous
#include <cuda_runtime.h>
#include <cuda_bf16.h>
#include <stdint.h>
#include <math.h>

// ---------------------------------------------------------------------------
// Problem constants
// ---------------------------------------------------------------------------
#define MTOK 16384        // B*N tokens
#define DDIM 1024         // hidden dim
#define NEXP 8            // experts
#define FDIM 512          // expert dim
#define KEF  4096         // NEXP*FDIM

// GEMM tiling
#define BM 128
#define BN 128
#define BK 32             // bf16 per stage (64 bytes per logical row)
#define NSTAGE 3
#define STAGE_BYTES 32768         // Ahi/Alo/Bhi/Blo, 8KB each
#define OFF_AHI 0
#define OFF_ALO 8192
#define OFF_BHI 16384
#define OFF_BLO 24576
#define SMEM_MAIN (NSTAGE * STAGE_BYTES)
#define SMEM_TOTAL (SMEM_MAIN + 4096)      // + b2 bias tile (8x128 fp32)

// ---------------------------------------------------------------------------
// Global scratch (static __device__ — no allocation)
// ---------------------------------------------------------------------------
static __device__ __align__(256) float         g_router[MTOK * NEXP];
static __device__ __align__(256) __nv_bfloat16 g_xhi[(size_t)MTOK * DDIM];
static __device__ __align__(256) __nv_bfloat16 g_xlo[(size_t)MTOK * DDIM];
static __device__ __align__(256) __nv_bfloat16 g_w1t_hi[(size_t)NEXP * FDIM * DDIM]; // [e][f][d]
static __device__ __align__(256) __nv_bfloat16 g_w1t_lo[(size_t)NEXP * FDIM * DDIM];
static __device__ __align__(256) __nv_bfloat16 g_w2t_hi[(size_t)DDIM * KEF];         // [d][ef]
static __device__ __align__(256) __nv_bfloat16 g_w2t_lo[(size_t)DDIM * KEF];
static __device__ __align__(256) __nv_bfloat16 g_ghi[(size_t)MTOK * KEF];
static __device__ __align__(256) __nv_bfloat16 g_glo[(size_t)MTOK * KEF];

// ---------------------------------------------------------------------------
// Helpers (base ISA only: cp.async, ldmatrix, mma.sync — no 'a' features)
// ---------------------------------------------------------------------------
__device__ __forceinline__ uint32_t ea_smem_u32(const void* p) {
    uint32_t a;
    asm("{ .reg .u64 t; cvta.to.shared.u64 t, %1; cvt.u32.u64 %0, t; }" : "=r"(a) : "l"(p));
    return a;
}
// Logical (row r, 16B-chunk c in 0..3) -> conflict-free physical byte offset.
// Two 64B logical rows share one 128B physical row; 3-bit xor swizzle.
__device__ __forceinline__ uint32_t ea_sw(int r, int c) {
    return ((uint32_t)(r >> 1) << 7) |
           ((uint32_t)(((((r & 1) << 2) | c) ^ ((r >> 1) & 7))) << 4);
}
__device__ __forceinline__ void ea_cp16(uint32_t s, const void* g) {
    asm volatile("cp.async.cg.shared.global [%0], [%1], 16;\n" :: "r"(s), "l"(g));
}
__device__ __forceinline__ void ea_cp_commit() { asm volatile("cp.async.commit_group;\n"); }
template <int N>
__device__ __forceinline__ void ea_cp_wait() { asm volatile("cp.async.wait_group %0;\n" :: "n"(N)); }

__device__ __forceinline__ void ea_ldsm4(uint32_t* r, uint32_t a) {
    asm volatile("ldmatrix.sync.aligned.m8n8.x4.shared.b16 {%0,%1,%2,%3}, [%4];\n"
                 : "=r"(r[0]), "=r"(r[1]), "=r"(r[2]), "=r"(r[3]) : "r"(a));
}
__device__ __forceinline__ void ea_mma(float* d, const uint32_t* a, uint32_t b0, uint32_t b1) {
    asm volatile(
        "mma.sync.aligned.m16n8k16.row.col.f32.bf16.bf16.f32 "
        "{%0,%1,%2,%3}, {%4,%5,%6,%7}, {%8,%9}, {%0,%1,%2,%3};\n"
        : "+f"(d[0]), "+f"(d[1]), "+f"(d[2]), "+f"(d[3])
        : "r"(a[0]), "r"(a[1]), "r"(a[2]), "r"(a[3]), "r"(b0), "r"(b1));
}
__device__ __forceinline__ uint32_t ea_pack2(__nv_bfloat16 a, __nv_bfloat16 b) {
    return (uint32_t)__bfloat16_as_ushort(a) | ((uint32_t)__bfloat16_as_ushort(b) << 16);
}
__device__ __forceinline__ void ea_split(float v, __nv_bfloat16& h, __nv_bfloat16& l) {
    h = __float2bfloat16(v);
    l = __float2bfloat16(v - __bfloat162float(h));
}
__device__ __forceinline__ float ea_gelu(float v) {
    return 0.5f * v * (1.0f + erff(v * 0.70710678118654752f));
}

// ---------------------------------------------------------------------------
// Router: softmax(x@Wr + br) per token
// ---------------------------------------------------------------------------
__global__ void __launch_bounds__(256) router_kernel(
    const float* __restrict__ x, const float* __restrict__ Wr, const float* __restrict__ br)
{
    const int t = blockIdx.x;
    __shared__ float xs[DDIM];
    __shared__ float logits[NEXP];
    const float* xrow = x + (size_t)t * DDIM;
    for (int i = threadIdx.x; i < DDIM; i += blockDim.x) xs[i] = xrow[i];
    __syncthreads();
    const int warp = threadIdx.x >> 5, lane = threadIdx.x & 31;
    float acc = 0.0f;
    for (int k = lane; k < DDIM; k += 32) acc = fmaf(xs[k], Wr[k * NEXP + warp], acc);
    #pragma unroll
    for (int o = 16; o > 0; o >>= 1) acc += __shfl_xor_sync(0xffffffffu, acc, o);
    if (lane == 0) logits[warp] = acc + br[warp];
    __syncthreads();
    if (threadIdx.x == 0) {
        float mx = logits[0];
        #pragma unroll
        for (int e = 1; e < NEXP; e++) mx = fmaxf(mx, logits[e]);
        float ex[NEXP]; float s = 0.0f;
        #pragma unroll
        for (int e = 0; e < NEXP; e++) { ex[e] = expf(logits[e] - mx); s += ex[e]; }
        float inv = 1.0f / s;
        #pragma unroll
        for (int e = 0; e < NEXP; e++) g_router[t * NEXP + e] = ex[e] * inv;
    }
}

// ---------------------------------------------------------------------------
// fp32 -> bf16 hi/lo elementwise conversion of x
// ---------------------------------------------------------------------------
__global__ void __launch_bounds__(256) convert_x_kernel(const float* __restrict__ x)
{
    size_t i = (size_t)blockIdx.x * 256 + threadIdx.x;   // covers 4 floats
    float4 v = ((const float4*)x)[i];
    __nv_bfloat16 h0, h1, h2, h3, l0, l1, l2, l3;
    ea_split(v.x, h0, l0); ea_split(v.y, h1, l1);
    ea_split(v.z, h2, l2); ea_split(v.w, h3, l3);
    ((uint2*)g_xhi)[i] = make_uint2(ea_pack2(h0, h1), ea_pack2(h2, h3));
    ((uint2*)g_xlo)[i] = make_uint2(ea_pack2(l0, l1), ea_pack2(l2, l3));
}

// ---------------------------------------------------------------------------
// Transposing split: src[rows][cols] fp32 -> dst[cols][rows] bf16 hi/lo
// WHICH==0: W1 -> g_w1t (per-expert via z), WHICH==1: W2 -> g_w2t
// ---------------------------------------------------------------------------
template <int WHICH>
__global__ void __launch_bounds__(256) transpose_split_kernel(
    const float* __restrict__ src, int rows, int cols)
{
    __shared__ float tile[32][33];
    const size_t zoff = (size_t)blockIdx.z * rows * cols;
    const float* s = src + zoff;
    __nv_bfloat16* dhi = (WHICH == 0 ? g_w1t_hi : g_w2t_hi) + zoff;
    __nv_bfloat16* dlo = (WHICH == 0 ? g_w1t_lo : g_w2t_lo) + zoff;

    int x = blockIdx.x * 32 + threadIdx.x;
    int y0 = blockIdx.y * 32;
    #pragma unroll
    for (int j = 0; j < 32; j += 8)
        tile[threadIdx.y + j][threadIdx.x] = s[(size_t)(y0 + threadIdx.y + j) * cols + x];
    __syncthreads();
    int xo = blockIdx.y * 32 + threadIdx.x;
    int yo = blockIdx.x * 32;
    #pragma unroll
    for (int j = 0; j < 32; j += 8) {
        float v = tile[threadIdx.x][threadIdx.y + j];
        __nv_bfloat16 h, l; ea_split(v, h, l);
        size_t o = (size_t)(yo + threadIdx.y + j) * rows + xo;
        dhi[o] = h; dlo[o] = l;
    }
}

// ---------------------------------------------------------------------------
// GEMM via mma.sync bf16x3. MODE 0 = FC1 (gelu epilogue), MODE 1 = FC2.
// Block 128x128, BK=32, 256 threads, warp grid 2(m) x 4(n), warp tile 64x32.
// 3-stage cp.async pipeline, xor-swizzled smem, ldmatrix fragments.
// ---------------------------------------------------------------------------
template <int MODE>
__global__ void __launch_bounds__(256, 1) gemm_mma_kernel(
    const float* __restrict__ bias,   // b1 [E,F] or b2 [E,D]
    float* __restrict__ out)          // MODE 1 only
{
    extern __shared__ char smem[];
    const uint32_t sb = ea_smem_u32(smem);
    const int tid = threadIdx.x;
    const int wid = tid >> 5, lane = tid & 31;
    const int wm = wid & 1, wn = wid >> 1;
    const int bn0 = blockIdx.x * BN;
    const int bm0 = blockIdx.y * BM;
    const int e = (MODE == 0) ? blockIdx.z : 0;

    const __nv_bfloat16 *Ahi, *Alo, *Bhi, *Blo;
    int lda, ldb, nk;
    if (MODE == 0) {
        Ahi = g_xhi; Alo = g_xlo; lda = DDIM;
        size_t wo = (size_t)e * FDIM * DDIM;
        Bhi = g_w1t_hi + wo; Blo = g_w1t_lo + wo; ldb = DDIM;
        nk = DDIM / BK;
    } else {
        Ahi = g_ghi; Alo = g_glo; lda = KEF;
        Bhi = g_w2t_hi; Blo = g_w2t_lo; ldb = KEF;
        nk = KEF / BK;
    }

    // FC2: stage b2 tile [8][BN] into smem once (read in epilogue).
    if (MODE == 1) {
        float* b2s = (float*)(smem + SMEM_MAIN);
        #pragma unroll
        for (int it = 0; it < 4; it++) {
            int idx = tid + it * 256;               // 1024 entries
            b2s[idx] = bias[(idx >> 7) * DDIM + bn0 + (idx & 127)];
        }
    }

    float acc[4][4][4];
    #pragma unroll
    for (int a = 0; a < 4; a++)
        #pragma unroll
        for (int b = 0; b < 4; b++)
            #pragma unroll
            for (int c = 0; c < 4; c++) acc[a][b][c] = 0.0f;

    auto load_stage = [&](int stg, int kk) {
        uint32_t base = sb + stg * STAGE_BYTES;
        #pragma unroll
        for (int it = 0; it < 2; it++) {
            int idx = tid + it * 256;
            int r = idx >> 2, c = idx & 3;
            uint32_t so = ea_sw(r, c);
            size_t ga = (size_t)(bm0 + r) * lda + kk + c * 8;
            size_t gb = (size_t)(bn0 + r) * ldb + kk + c * 8;
            ea_cp16(base + OFF_AHI + so, Ahi + ga);
            ea_cp16(base + OFF_ALO + so, Alo + ga);
            ea_cp16(base + OFF_BHI + so, Bhi + gb);
            ea_cp16(base + OFF_BLO + so, Blo + gb);
        }
    };

    auto compute_stage = [&](int stg) {
        uint32_t base = sb + stg * STAGE_BYTES;
        #pragma unroll
        for (int s = 0; s < 2; s++) {          // two k16 steps per BK
            uint32_t ah[4][4], al[4][4], bh[2][4], bl[2][4];
            const int arow = wm * 64 + (lane & 7) + ((lane >> 3) & 1) * 8;
            const int acol = s * 2 + ((lane >> 4) & 1);
            #pragma unroll
            for (int mi = 0; mi < 4; mi++) {
                uint32_t off = ea_sw(arow + mi * 16, acol);
                ea_ldsm4(ah[mi], base + OFF_AHI + off);
                ea_ldsm4(al[mi], base + OFF_ALO + off);
            }
            const int brow = wn * 32 + (lane & 7) + ((lane >> 4) & 1) * 8;
            const int bcol = s * 2 + ((lane >> 3) & 1);
            #pragma unroll
            for (int bi = 0; bi < 2; bi++) {
                uint32_t off = ea_sw(brow + bi * 16, bcol);
                ea_ldsm4(bh[bi], base + OFF_BHI + off);
                ea_ldsm4(bl[bi], base + OFF_BLO + off);
            }
            #pragma unroll
            for (int mi = 0; mi < 4; mi++) {
                #pragma unroll
                for (int ni = 0; ni < 4; ni++) {
                    uint32_t b0h = bh[ni >> 1][(ni & 1) * 2], b1h = bh[ni >> 1][(ni & 1) * 2 + 1];
                    uint32_t b0l = bl[ni >> 1][(ni & 1) * 2], b1l = bl[ni >> 1][(ni & 1) * 2 + 1];
                    ea_mma(acc[mi][ni], ah[mi], b0h, b1h);   // hi*hi
                    ea_mma(acc[mi][ni], ah[mi], b0l, b1l);   // hi*lo
                    ea_mma(acc[mi][ni], al[mi], b0h, b1h);   // lo*hi
                }
            }
        }
    };

    // 3-stage pipeline
    load_stage(0, 0);        ea_cp_commit();
    load_stage(1, BK);       ea_cp_commit();
    load_stage(2, 2 * BK);   ea_cp_commit();
    ea_cp_wait<2>();
    __syncthreads();

    #pragma unroll 1
    for (int ck = 0; ck < nk; ck++) {
        compute_stage(ck % 3);
        __syncthreads();
        if (ck + 3 < nk) {
            load_stage(ck % 3, (ck + 3) * BK);
            ea_cp_commit();
            ea_cp_wait<2>();
        } else {
            ea_cp_wait<0>();
        }
        __syncthreads();
    }

    // ------------------------------ epilogue -------------------------------
    const int lrow = lane >> 2;          // 0..7
    const int lcol = (lane & 3) << 1;    // 0,2,4,6

    if (MODE == 0) {
        #pragma unroll
        for (int mi = 0; mi < 4; mi++) {
            #pragma unroll
            for (int p = 0; p < 2; p++) {
                const int m = bm0 + wm * 64 + mi * 16 + lrow + p * 8;
                const float wr = g_router[m * NEXP + e];
                const size_t rowo = (size_t)m * KEF + e * FDIM + bn0 + wn * 32;
                #pragma unroll
                for (int ni = 0; ni < 4; ni++) {
                    const int n = wn * 32 + ni * 8 + lcol;     // within BN tile
                    float v0 = acc[mi][ni][p * 2 + 0] + bias[e * FDIM + bn0 + n];
                    float v1 = acc[mi][ni][p * 2 + 1] + bias[e * FDIM + bn0 + n + 1];
                    v0 = ea_gelu(v0) * wr;
                    v1 = ea_gelu(v1) * wr;
                    __nv_bfloat16 h0, l0, h1, l1;
                    ea_split(v0, h0, l0); ea_split(v1, h1, l1);
                    *(uint32_t*)(g_ghi + rowo + ni * 8 + lcol) = ea_pack2(h0, h1);
                    *(uint32_t*)(g_glo + rowo + ni * 8 + lcol) = ea_pack2(l0, l1);
                }
            }
        }
    } else {
        const float* b2s = (const float*)(smem + SMEM_MAIN);
        #pragma unroll
        for (int mi = 0; mi < 4; mi++) {
            #pragma unroll
            for (int p = 0; p < 2; p++) {
                const int m = bm0 + wm * 64 + mi * 16 + lrow + p * 8;
                float4 w0 = *(const float4*)(g_router + (size_t)m * NEXP);
                float4 w1 = *(const float4*)(g_router + (size_t)m * NEXP + 4);
                float wr[NEXP] = {w0.x, w0.y, w0.z, w0.w, w1.x, w1.y, w1.z, w1.w};
                float* orow = out + (size_t)m * DDIM + bn0 + wn * 32;
                #pragma unroll
                for (int ni = 0; ni < 4; ni++) {
                    const int n = wn * 32 + ni * 8 + lcol;
                    float bias0 = 0.0f, bias1 = 0.0f;
                    #pragma unroll
                    for (int ee = 0; ee < NEXP; ee++) {
                        bias0 = fmaf(wr[ee], b2s[ee * BN + n], bias0);
                        bias1 = fmaf(wr[ee], b2s[ee * BN + n + 1], bias1);
                    }
                    float2 res = make_float2(acc[mi][ni][p * 2 + 0] + bias0,
                                             acc[mi][ni][p * 2 + 1] + bias1);
                    *(float2*)(orow + ni * 8 + lcol) = res;
                }
            }
        }
    }
}

// ---------------------------------------------------------------------------
extern "C" void kernel_launch(void* const* d_in, const int* in_sizes, int n_in,
                              void* d_out, int out_size)
{
    const float* x  = (const float*)d_in[0];
    const float* W1 = (const float*)d_in[1];
    const float* b1 = (const float*)d_in[2];
    const float* W2 = (const float*)d_in[3];
    const float* b2 = (const float*)d_in[4];
    const float* Wr = (const float*)d_in[5];
    const float* br = (const float*)d_in[6];
    float* out = (float*)d_out;

    cudaFuncSetAttribute(gemm_mma_kernel<0>, cudaFuncAttributeMaxDynamicSharedMemorySize, SMEM_TOTAL);
    cudaFuncSetAttribute(gemm_mma_kernel<1>, cudaFuncAttributeMaxDynamicSharedMemorySize, SMEM_TOTAL);

    router_kernel<<<MTOK, 256>>>(x, Wr, br);
    convert_x_kernel<<<(MTOK * DDIM / 4) / 256, 256>>>(x);
    transpose_split_kernel<0><<<dim3(FDIM / 32, DDIM / 32, NEXP), dim3(32, 8)>>>(W1, DDIM, FDIM);
    transpose_split_kernel<1><<<dim3(DDIM / 32, KEF / 32, 1), dim3(32, 8)>>>(W2, KEF, DDIM);

    dim3 g1(FDIM / BN, MTOK / BM, NEXP);   // (4, 128, 8)
    gemm_mma_kernel<0><<<g1, 256, SMEM_TOTAL>>>(b1, nullptr);

    dim3 g2(DDIM / BN, MTOK / BM, 1);      // (8, 128)
    gemm_mma_kernel<1><<<g2, 256, SMEM_TOTAL>>>(b2, out);
}